// round 9
// baseline (speedup 1.0000x reference)
#include <cuda_runtime.h>
#include <cuda_bf16.h>

// out[b, d] = x[b, d] * clamp(diagonal[d], -0.95, 0.95)
// BATCH = 16384, LATENT_DIM = 8192, fp32. 1 GiB streamed, HBM-bound.
//
// R9: store-policy probe. Geometry = R7 (MLP=8, best profiled DRAM%).
//     Reads keep __ldcs (evict-first, read-once). Stores switch from
//     __stcs (evict-first -> immediate writeback -> fine R/W interleave)
//     to DEFAULT write-back: L2 (126 MB) batches dirty evictions, giving
//     the DRAM scheduler longer same-direction write runs and fewer bus
//     turnarounds.

#define LATENT_DIM 8192
#define BATCH 16384
#define COLS4 (LATENT_DIM / 4)        // 2048 float4 per row
#define TPB 256
#define UNROLL 8                      // TPB * UNROLL == COLS4 (one row per CTA)

__global__ __launch_bounds__(TPB)
void diag_linear_kernel(const float4* __restrict__ x,
                        const float4* __restrict__ diag,
                        float4* __restrict__ out) {
    const int col = threadIdx.x;                         // 0 .. 255
    const long long off = (long long)blockIdx.x * COLS4 + col;

    // 8 independent front-batched reads, evict-first (read exactly once).
    float4 v[UNROLL];
#pragma unroll
    for (int k = 0; k < UNROLL; k++)
        v[k] = __ldcs(&x[off + k * TPB]);

    // Apply clamped diagonal (32 KiB, L1/L2-hot).
#pragma unroll
    for (int k = 0; k < UNROLL; k++) {
        float4 s = __ldg(&diag[col + k * TPB]);
        s.x = fminf(fmaxf(s.x, -0.95f), 0.95f);
        s.y = fminf(fmaxf(s.y, -0.95f), 0.95f);
        s.z = fminf(fmaxf(s.z, -0.95f), 0.95f);
        s.w = fminf(fmaxf(s.w, -0.95f), 0.95f);
        v[k].x *= s.x;
        v[k].y *= s.y;
        v[k].z *= s.z;
        v[k].w *= s.w;
    }

    // Default write-back stores: let L2 batch dirty-line evictions into
    // long DRAM write bursts instead of evicting each line immediately.
#pragma unroll
    for (int k = 0; k < UNROLL; k++)
        out[off + k * TPB] = v[k];
}

extern "C" void kernel_launch(void* const* d_in, const int* in_sizes, int n_in,
                              void* d_out, int out_size) {
    const float4* x    = (const float4*)d_in[0];
    const float4* diag = (const float4*)d_in[1];
    float4* out        = (float4*)d_out;

    diag_linear_kernel<<<BATCH, TPB>>>(x, diag, out);
}

// round 10
// speedup vs baseline: 1.0103x; 1.0103x over previous
#include <cuda_runtime.h>
#include <cuda_bf16.h>

// out[b, d] = x[b, d] * clamp(diagonal[d], -0.95, 0.95)
// BATCH = 16384, LATENT_DIM = 8192, fp32. 1 GiB streamed, HBM-bound.
//
// FINAL (= R6 config, best wall time 157.25us, DRAM 85.1%, 6744 GB/s).
// Nine-round search established a hard plateau at ~6.7-6.77 TB/s
// (84-85% of 8 TB/s spec) = the DRAM read/write-turnaround floor for a
// 1:1 streaming mix. Non-levers (all tested, all neutral or worse):
// 256-bit accesses, MLP 8/16, persistence, write-back stores, ld hints,
// launch geometry. Binding constraints: occupancy must stay >= ~50%
// (R3 regression), __stcs beats write-back by ~1%.
//
// Config: float4 streams, MLP=4, TPB=256, 2 column-blocks x 16384 rows,
// regs=32 -> 82% occupancy, __ldcs reads (read-once), __stcs writes.

#define LATENT_DIM 8192
#define BATCH 16384
#define COLS4 (LATENT_DIM / 4)        // 2048 float4 per row
#define TPB 256
#define UNROLL 4
#define CHUNK (TPB * UNROLL)          // 1024 float4 per block
#define BLOCKS_X (COLS4 / CHUNK)      // 2 column-blocks per row

__global__ __launch_bounds__(TPB)
void diag_linear_kernel(const float4* __restrict__ x,
                        const float4* __restrict__ diag,
                        float4* __restrict__ out) {
    const int base_col = blockIdx.x * CHUNK + threadIdx.x;   // warp-coalesced
    const long long off = (long long)blockIdx.y * COLS4 + base_col;

    // 4 independent front-batched reads (MLP=4), evict-first: x is read once.
    float4 v[UNROLL];
#pragma unroll
    for (int k = 0; k < UNROLL; k++)
        v[k] = __ldcs(&x[off + k * TPB]);

    // Clamped diagonal: 32 KiB, L1/L2-resident after first wave.
#pragma unroll
    for (int k = 0; k < UNROLL; k++) {
        float4 s = __ldg(&diag[base_col + k * TPB]);
        s.x = fminf(fmaxf(s.x, -0.95f), 0.95f);
        s.y = fminf(fmaxf(s.y, -0.95f), 0.95f);
        s.z = fminf(fmaxf(s.z, -0.95f), 0.95f);
        s.w = fminf(fmaxf(s.w, -0.95f), 0.95f);
        v[k].x *= s.x;
        v[k].y *= s.y;
        v[k].z *= s.z;
        v[k].w *= s.w;
    }

    // Streaming stores: output never re-read; evict-first beats write-back.
#pragma unroll
    for (int k = 0; k < UNROLL; k++)
        __stcs(&out[off + k * TPB], v[k]);
}

extern "C" void kernel_launch(void* const* d_in, const int* in_sizes, int n_in,
                              void* d_out, int out_size) {
    const float4* x    = (const float4*)d_in[0];
    const float4* diag = (const float4*)d_in[1];
    float4* out        = (float4*)d_out;

    dim3 grid(BLOCKS_X, BATCH, 1);
    diag_linear_kernel<<<grid, TPB>>>(x, diag, out);
}

// round 11
// speedup vs baseline: 1.0108x; 1.0004x over previous
#include <cuda_runtime.h>
#include <cuda_bf16.h>

// out[b, d] = x[b, d] * clamp(diagonal[d], -0.95, 0.95)
// BATCH = 16384, LATENT_DIM = 8192, fp32. 1 GiB streamed, HBM-bound.
//
// R11 (terminal): best-profiled config (R7: MLP=8, one row per CTA,
// 6768 GB/s) with diag loads hoisted ahead of the x stream so the clamp
// chain is ready before the first DRAM load returns. Ten-round search
// established a hard plateau at ~6.7-6.77 TB/s (84-85% of 8 TB/s spec):
// the DRAM read/write-turnaround floor for a 1:1 streaming mix.
// Closed axes: vector width (128/256b), MLP (1/4/8/16, peak at 8),
// occupancy (non-binding >= 50%), persistence (regression), ld hints
// (neutral), store policy (__stcs > write-back), geometry (neutral).

#define LATENT_DIM 8192
#define BATCH 16384
#define COLS4 (LATENT_DIM / 4)        // 2048 float4 per row
#define TPB 256
#define UNROLL 8                      // TPB * UNROLL == COLS4 (one row per CTA)

__global__ __launch_bounds__(TPB)
void diag_linear_kernel(const float4* __restrict__ x,
                        const float4* __restrict__ diag,
                        float4* __restrict__ out) {
    const int col = threadIdx.x;                         // 0 .. 255
    const long long off = (long long)blockIdx.x * COLS4 + col;

    // Diag first: L1/L2-hot (32 KiB), returns in ~30-230 cyc — ready well
    // before the DRAM x loads land. Clamp immediately (hidden work).
    float4 d[UNROLL];
#pragma unroll
    for (int k = 0; k < UNROLL; k++)
        d[k] = __ldg(&diag[col + k * TPB]);

    // 8 independent front-batched DRAM reads (MLP=8, best-measured point),
    // evict-first: x is read exactly once.
    float4 v[UNROLL];
#pragma unroll
    for (int k = 0; k < UNROLL; k++)
        v[k] = __ldcs(&x[off + k * TPB]);

#pragma unroll
    for (int k = 0; k < UNROLL; k++) {
        float4 s = d[k];
        s.x = fminf(fmaxf(s.x, -0.95f), 0.95f);
        s.y = fminf(fmaxf(s.y, -0.95f), 0.95f);
        s.z = fminf(fmaxf(s.z, -0.95f), 0.95f);
        s.w = fminf(fmaxf(s.w, -0.95f), 0.95f);
        v[k].x *= s.x;
        v[k].y *= s.y;
        v[k].z *= s.z;
        v[k].w *= s.w;
    }

    // Batched streaming stores: output never re-read; evict-first beats
    // write-back (measured R9).
#pragma unroll
    for (int k = 0; k < UNROLL; k++)
        __stcs(&out[off + k * TPB], v[k]);
}

extern "C" void kernel_launch(void* const* d_in, const int* in_sizes, int n_in,
                              void* d_out, int out_size) {
    const float4* x    = (const float4*)d_in[0];
    const float4* diag = (const float4*)d_in[1];
    float4* out        = (float4*)d_out;

    diag_linear_kernel<<<BATCH, TPB>>>(x, diag, out);
}

// round 12
// speedup vs baseline: 1.0116x; 1.0008x over previous
#include <cuda_runtime.h>
#include <cuda_bf16.h>

// out[b, d] = x[b, d] * clamp(diagonal[d], -0.95, 0.95)
// BATCH = 16384, LATENT_DIM = 8192, fp32. 1 GiB streamed, HBM-bound.
//
// FINAL. Eleven-round search pinned this kernel at the B300 DRAM
// read/write-turnaround floor: 6.70-6.77 TB/s (84-85% of 8 TB/s spec),
// profiled 150.7-152.0 us across every configuration tried. Closed axes:
//   - vector width 128b vs 256b: neutral (LTS/DRAM path-independent)
//   - per-thread MLP 1/4/8/16: 6500/6718/6768/6727 GB/s (all ~1% band)
//   - occupancy 33-83%: non-binding above ~50%; binding below (R3: -5%)
//   - persistent single-wave launch: regression (occupancy-driven)
//   - read hints (default/__ldcs/__ldlu): neutral
//   - store policy: __stcs (evict-first) beats write-back by ~1% (R9)
//   - launch geometry (6 variants): neutral
//
// Chosen config = best observed wall time (157.25 us) and the most robust
// plateau point: float4 streams, MLP=4, TPB=256, grid (2, 16384),
// regs=32 -> 82.5% occupancy, __ldcs reads, __stcs writes.

#define LATENT_DIM 8192
#define BATCH 16384
#define COLS4 (LATENT_DIM / 4)        // 2048 float4 per row
#define TPB 256
#define UNROLL 4
#define CHUNK (TPB * UNROLL)          // 1024 float4 per block
#define BLOCKS_X (COLS4 / CHUNK)      // 2 column-blocks per row

__global__ __launch_bounds__(TPB)
void diag_linear_kernel(const float4* __restrict__ x,
                        const float4* __restrict__ diag,
                        float4* __restrict__ out) {
    const int base_col = blockIdx.x * CHUNK + threadIdx.x;   // warp-coalesced
    const long long off = (long long)blockIdx.y * COLS4 + base_col;

    // 4 independent front-batched DRAM reads (MLP=4), evict-first: x is
    // read exactly once.
    float4 v[UNROLL];
#pragma unroll
    for (int k = 0; k < UNROLL; k++)
        v[k] = __ldcs(&x[off + k * TPB]);

    // Clamped diagonal: 32 KiB, L1/L2-resident after the first wave.
#pragma unroll
    for (int k = 0; k < UNROLL; k++) {
        float4 s = __ldg(&diag[base_col + k * TPB]);
        s.x = fminf(fmaxf(s.x, -0.95f), 0.95f);
        s.y = fminf(fmaxf(s.y, -0.95f), 0.95f);
        s.z = fminf(fmaxf(s.z, -0.95f), 0.95f);
        s.w = fminf(fmaxf(s.w, -0.95f), 0.95f);
        v[k].x *= s.x;
        v[k].y *= s.y;
        v[k].z *= s.z;
        v[k].w *= s.w;
    }

    // Streaming stores: output never re-read; evict-first beats write-back.
#pragma unroll
    for (int k = 0; k < UNROLL; k++)
        __stcs(&out[off + k * TPB], v[k]);
}

extern "C" void kernel_launch(void* const* d_in, const int* in_sizes, int n_in,
                              void* d_out, int out_size) {
    const float4* x    = (const float4*)d_in[0];
    const float4* diag = (const float4*)d_in[1];
    float4* out        = (float4*)d_out;

    dim3 grid(BLOCKS_X, BATCH, 1);
    diag_linear_kernel<<<grid, TPB>>>(x, diag, out);
}

// round 13
// speedup vs baseline: 1.0118x; 1.0002x over previous
#include <cuda_runtime.h>
#include <cuda_bf16.h>

// out[b, d] = x[b, d] * clamp(diagonal[d], -0.95, 0.95)
// BATCH = 16384, LATENT_DIM = 8192, fp32. 1 GiB streamed, HBM-bound.
//
// TERMINAL KERNEL (3rd submission of this config; best wall 157.25 us).
// Twelve-round search pinned the op at the B300 DRAM read/write-turnaround
// floor: 6.70-6.77 TB/s (84-85% of 8 TB/s spec), profiled 151.0-152.4 us
// for THIS EXACT BINARY across draws — the remaining spread is noise.
//
// Mapped axes (all closed):
//   - vector width 128b vs 256b LDG/STG: neutral
//   - per-thread MLP 1/4/8/16: +3% from 1->4, flat after
//   - occupancy 33-83%: non-binding above ~50%, binding below (R3)
//   - persistent single-wave launch: regression (occupancy-driven)
//   - read hints default/__ldcs/__ldlu: neutral
//   - store policy: __stcs beats write-back by ~1% (R9)
//   - load ordering / launch geometry (7 variants): neutral
//
// Config: float4 streams, MLP=4, TPB=256, grid (2, 16384), regs=32
// -> 82.5% occupancy, __ldcs reads (read-once), __stcs writes.

#define LATENT_DIM 8192
#define BATCH 16384
#define COLS4 (LATENT_DIM / 4)        // 2048 float4 per row
#define TPB 256
#define UNROLL 4
#define CHUNK (TPB * UNROLL)          // 1024 float4 per block
#define BLOCKS_X (COLS4 / CHUNK)      // 2 column-blocks per row

__global__ __launch_bounds__(TPB)
void diag_linear_kernel(const float4* __restrict__ x,
                        const float4* __restrict__ diag,
                        float4* __restrict__ out) {
    const int base_col = blockIdx.x * CHUNK + threadIdx.x;   // warp-coalesced
    const long long off = (long long)blockIdx.y * COLS4 + base_col;

    // 4 independent front-batched DRAM reads (MLP=4), evict-first: x is
    // read exactly once.
    float4 v[UNROLL];
#pragma unroll
    for (int k = 0; k < UNROLL; k++)
        v[k] = __ldcs(&x[off + k * TPB]);

    // Clamped diagonal: 32 KiB, L1/L2-resident after the first wave.
#pragma unroll
    for (int k = 0; k < UNROLL; k++) {
        float4 s = __ldg(&diag[base_col + k * TPB]);
        s.x = fminf(fmaxf(s.x, -0.95f), 0.95f);
        s.y = fminf(fmaxf(s.y, -0.95f), 0.95f);
        s.z = fminf(fmaxf(s.z, -0.95f), 0.95f);
        s.w = fminf(fmaxf(s.w, -0.95f), 0.95f);
        v[k].x *= s.x;
        v[k].y *= s.y;
        v[k].z *= s.z;
        v[k].w *= s.w;
    }

    // Streaming stores: output never re-read; evict-first beats write-back.
#pragma unroll
    for (int k = 0; k < UNROLL; k++)
        __stcs(&out[off + k * TPB], v[k]);
}

extern "C" void kernel_launch(void* const* d_in, const int* in_sizes, int n_in,
                              void* d_out, int out_size) {
    const float4* x    = (const float4*)d_in[0];
    const float4* diag = (const float4*)d_in[1];
    float4* out        = (float4*)d_out;

    dim3 grid(BLOCKS_X, BATCH, 1);
    diag_linear_kernel<<<grid, TPB>>>(x, diag, out);
}

// round 14
// speedup vs baseline: 1.0120x; 1.0002x over previous
#include <cuda_runtime.h>
#include <cuda_bf16.h>

// out[b, d] = x[b, d] * clamp(diagonal[d], -0.95, 0.95)
// BATCH = 16384, LATENT_DIM = 8192, fp32. 1 GiB streamed, HBM-bound.
//
// TERMINAL KERNEL — final. Four draws of this exact binary:
//   wall {157.25, 157.73, 157.54, 157.50} us
//   profiled {151.1, 151.0, 152.4, 150.9} us, DRAM 84.5-85.4%, ~6.75 TB/s.
// Thirteen rounds mapped every axis; the op sits at the B300 DRAM
// read/write-turnaround floor for a 1:1 streaming mix. Traffic is minimal
// (1 GiB, each byte moved once, fully coalesced, diag cache-resident).
//
// Closed axes: vector width (128/256b), MLP (1/4/8/16), occupancy
// (33-83%), persistence, read hints, store policy (__stcs wins),
// load ordering, 7 launch geometries.
//
// Config: float4 streams, MLP=4, TPB=256, grid (2, 16384), regs=32
// -> 82.5% occupancy, __ldcs reads (read-once), __stcs writes.

#define LATENT_DIM 8192
#define BATCH 16384
#define COLS4 (LATENT_DIM / 4)        // 2048 float4 per row
#define TPB 256
#define UNROLL 4
#define CHUNK (TPB * UNROLL)          // 1024 float4 per block
#define BLOCKS_X (COLS4 / CHUNK)      // 2 column-blocks per row

__global__ __launch_bounds__(TPB)
void diag_linear_kernel(const float4* __restrict__ x,
                        const float4* __restrict__ diag,
                        float4* __restrict__ out) {
    const int base_col = blockIdx.x * CHUNK + threadIdx.x;   // warp-coalesced
    const long long off = (long long)blockIdx.y * COLS4 + base_col;

    // 4 independent front-batched DRAM reads (MLP=4), evict-first: x is
    // read exactly once.
    float4 v[UNROLL];
#pragma unroll
    for (int k = 0; k < UNROLL; k++)
        v[k] = __ldcs(&x[off + k * TPB]);

    // Clamped diagonal: 32 KiB, L1/L2-resident after the first wave.
#pragma unroll
    for (int k = 0; k < UNROLL; k++) {
        float4 s = __ldg(&diag[base_col + k * TPB]);
        s.x = fminf(fmaxf(s.x, -0.95f), 0.95f);
        s.y = fminf(fmaxf(s.y, -0.95f), 0.95f);
        s.z = fminf(fmaxf(s.z, -0.95f), 0.95f);
        s.w = fminf(fmaxf(s.w, -0.95f), 0.95f);
        v[k].x *= s.x;
        v[k].y *= s.y;
        v[k].z *= s.z;
        v[k].w *= s.w;
    }

    // Streaming stores: output never re-read; evict-first beats write-back.
#pragma unroll
    for (int k = 0; k < UNROLL; k++)
        __stcs(&out[off + k * TPB], v[k]);
}

extern "C" void kernel_launch(void* const* d_in, const int* in_sizes, int n_in,
                              void* d_out, int out_size) {
    const float4* x    = (const float4*)d_in[0];
    const float4* diag = (const float4*)d_in[1];
    float4* out        = (float4*)d_out;

    dim3 grid(BLOCKS_X, BATCH, 1);
    diag_linear_kernel<<<grid, TPB>>>(x, diag, out);
}

// round 15
// speedup vs baseline: 1.0124x; 1.0004x over previous
#include <cuda_runtime.h>
#include <cuda_bf16.h>

// out[b, d] = x[b, d] * clamp(diagonal[d], -0.95, 0.95)
// BATCH = 16384, LATENT_DIM = 8192, fp32. 1 GiB streamed, HBM-bound.
//
// TERMINAL KERNEL — final, held. Five draws of this exact binary:
//   wall {157.25, 157.73, 157.54, 157.50, 157.47} us (sigma ~0.17us)
//   profiled 150.9-153.4 us, DRAM 83.9-85.4%, 6.65-6.76 TB/s
//   (run-to-run LTS/DRAM variation per the B300 microarch model).
// Fourteen rounds mapped every axis; the op sits at the B300 DRAM
// read/write-turnaround floor for a 1:1 streaming mix. Traffic is
// minimal: 1 GiB total, each byte moved exactly once, fully coalesced,
// diagonal (32 KiB) cache-resident.
//
// Closed axes (all bracketed both directions, deltas <= 1%):
//   vector width 128/256b - MLP 1/4/8/16 - occupancy 33-83% -
//   persistence - read hints (default/cs/lu) - store policy (cs > wb) -
//   load ordering - 7 launch geometries.
//
// Config: float4 streams, MLP=4, TPB=256, grid (2, 16384), regs=32
// -> 82.5% occupancy, __ldcs reads (read-once), __stcs writes.

#define LATENT_DIM 8192
#define BATCH 16384
#define COLS4 (LATENT_DIM / 4)        // 2048 float4 per row
#define TPB 256
#define UNROLL 4
#define CHUNK (TPB * UNROLL)          // 1024 float4 per block
#define BLOCKS_X (COLS4 / CHUNK)      // 2 column-blocks per row

__global__ __launch_bounds__(TPB)
void diag_linear_kernel(const float4* __restrict__ x,
                        const float4* __restrict__ diag,
                        float4* __restrict__ out) {
    const int base_col = blockIdx.x * CHUNK + threadIdx.x;   // warp-coalesced
    const long long off = (long long)blockIdx.y * COLS4 + base_col;

    // 4 independent front-batched DRAM reads (MLP=4), evict-first: x is
    // read exactly once.
    float4 v[UNROLL];
#pragma unroll
    for (int k = 0; k < UNROLL; k++)
        v[k] = __ldcs(&x[off + k * TPB]);

    // Clamped diagonal: 32 KiB, L1/L2-resident after the first wave.
#pragma unroll
    for (int k = 0; k < UNROLL; k++) {
        float4 s = __ldg(&diag[base_col + k * TPB]);
        s.x = fminf(fmaxf(s.x, -0.95f), 0.95f);
        s.y = fminf(fmaxf(s.y, -0.95f), 0.95f);
        s.z = fminf(fmaxf(s.z, -0.95f), 0.95f);
        s.w = fminf(fmaxf(s.w, -0.95f), 0.95f);
        v[k].x *= s.x;
        v[k].y *= s.y;
        v[k].z *= s.z;
        v[k].w *= s.w;
    }

    // Streaming stores: output never re-read; evict-first beats write-back.
#pragma unroll
    for (int k = 0; k < UNROLL; k++)
        __stcs(&out[off + k * TPB], v[k]);
}

extern "C" void kernel_launch(void* const* d_in, const int* in_sizes, int n_in,
                              void* d_out, int out_size) {
    const float4* x    = (const float4*)d_in[0];
    const float4* diag = (const float4*)d_in[1];
    float4* out        = (float4*)d_out;

    dim3 grid(BLOCKS_X, BATCH, 1);
    diag_linear_kernel<<<grid, TPB>>>(x, diag, out);
}